// round 16
// baseline (speedup 1.0000x reference)
#include <cuda_runtime.h>
#include <cuda_fp16.h>
#include <cstdint>

// Two-kernel split with PDL (programmatic dependent launch) overlap:
//   prep: fp16 EwT/EhT tables (1M exps once). Fires launch_dependents at
//         entry so main can start while prep runs.
//   main: stages act fp32->fp16 (independent of prep, overlaps it), then
//         griddepcontrol.wait, cp.async tables, GEMM M=64 N=128 K=128
//         (mma.sync.m16n8k16.f16), smem EhT epilogue. 3 CTAs/SM.

#define HDIM 128
#define NPTS 4096

__device__ __align__(256) __half g_EW[NPTS * HDIM];   // EwT [n][w]
__device__ __align__(256) __half g_EH[NPTS * HDIM];   // EhT [n][h]

#define NSTRIDE  272                   // 17*16 -> conflict-free ldmatrix/LDS
#define EW_OFF   0
#define EH_OFF   17408                 // 64*272
#define ACT_OFF  34816                 // +64*272
#define RED_OFF  69632                 // +128*272
#define SMEM_REQ 70656

__device__ __forceinline__ uint32_t smem_to_u32(const void* p) {
    uint32_t a;
    asm("{ .reg .u64 t; cvta.to.shared.u64 t, %1; cvt.u32.u64 %0, t; }" : "=r"(a) : "l"(p));
    return a;
}
__device__ __forceinline__ uint32_t f22h2(float a, float b) {
    __half2 h = __floats2half2_rn(a, b);
    return *reinterpret_cast<uint32_t*>(&h);
}
#define CP16(dst, src) \
    asm volatile("cp.async.cg.shared.global [%0], [%1], 16;" :: "r"(dst), "l"(src) : "memory")
#define CP_COMMIT() asm volatile("cp.async.commit_group;" ::: "memory")
#define CP_WAIT0()  asm volatile("cp.async.wait_group 0;" ::: "memory")

#define LDSM_X4(r0, r1, r2, r3, addr)                                          \
    asm volatile("ldmatrix.sync.aligned.m8n8.x4.shared.b16 {%0,%1,%2,%3}, [%4];" \
        : "=r"(r0), "=r"(r1), "=r"(r2), "=r"(r3) : "r"(addr))

#define MMA_F16(c, a, b0, b1)                                                  \
    asm volatile("mma.sync.aligned.m16n8k16.row.col.f32.f16.f16.f32 "           \
        "{%0,%1,%2,%3},{%4,%5,%6,%7},{%8,%9},{%0,%1,%2,%3};"                    \
        : "+f"((c)[0]), "+f"((c)[1]), "+f"((c)[2]), "+f"((c)[3])                \
        : "r"((a)[0]), "r"((a)[1]), "r"((a)[2]), "r"((a)[3]), "r"(b0), "r"(b1))

// 8 Gaussian factors from g0 (step 1/128), packed to uint4 of half2.
__device__ __forceinline__ void gauss8(float g0, float mval, float inv, uint4* o)
{
    float e[8];
    #pragma unroll
    for (int j = 0; j < 8; j++) {
        const float d = g0 + (float)j * (1.0f / 128.0f) - mval;
        e[j] = __expf(-(d * d * inv));
    }
    o->x = f22h2(e[0], e[1]); o->y = f22h2(e[2], e[3]);
    o->z = f22h2(e[4], e[5]); o->w = f22h2(e[6], e[7]);
}

// ---------------------------------------------------------------------------
// prep: 256 CTAs x 256 thr; thread handles 8 consecutive (n,j) values of both
// tables (same n for all 8 since 8 | 128). Fires launch_dependents at entry.
// ---------------------------------------------------------------------------
__global__ __launch_bounds__(256) void prep_kernel(
    const float* __restrict__ mu, const float* __restrict__ sigma)
{
    asm volatile("griddepcontrol.launch_dependents;");
    const int t  = blockIdx.x * 256 + threadIdx.x;   // 0 .. 65535
    const int n  = t >> 4;                           // 16 threads per n row
    const int j0 = (t & 15) * 8;                     // 8-col group

    const float2 m = ((const float2*)mu)[n];
    const float2 s = ((const float2*)sigma)[n];
    const float invy = 1.0f / (2.0f * s.y * s.y);
    const float invx = 1.0f / (2.0f * s.x * s.x);
    const float g0 = (float)j0 * (1.0f / 128.0f);

    uint4 ow, oh;
    gauss8(g0, m.y, invy, &ow);
    gauss8(g0, m.x, invx, &oh);
    *(uint4*)(g_EW + n * HDIM + j0) = ow;
    *(uint4*)(g_EH + n * HDIM + j0) = oh;
}

// ---------------------------------------------------------------------------
// main: grid (64 n-tiles, 8 b), 256 thr, 3 CTAs/SM.
// ---------------------------------------------------------------------------
__global__ __launch_bounds__(256, 3) void main_kernel(
    const float* __restrict__ act, float* __restrict__ out)
{
    extern __shared__ char smem[];
    const uint32_t sb = smem_to_u32(smem);

    const int tid = threadIdx.x;
    const int wid = tid >> 5, l = tid & 31;
    const int wm = wid & 1;            // n half: rows wm*32..+32
    const int wn = wid >> 1;           // h quarter: cols wn*32..+32
    const int b  = blockIdx.y;
    const int n0 = blockIdx.x * 64;

    // ---- Stage act fp32->fp16 (independent of prep; overlaps it) ----------
    const float4* g0p = (const float4*)(act + b * HDIM * HDIM);
    #pragma unroll
    for (int k = 0; k < 8; k++) {
        const int cid = k * 256 + tid;        // 0..2047 chunks
        const int r = cid >> 4, u = cid & 15;
        const float4 va = __ldg(&g0p[r * 32 + u * 2]);
        const float4 vb = __ldg(&g0p[r * 32 + u * 2 + 1]);
        uint4 o;
        o.x = f22h2(va.x, va.y); o.y = f22h2(va.z, va.w);
        o.z = f22h2(vb.x, vb.y); o.w = f22h2(vb.z, vb.w);
        *(uint4*)(smem + ACT_OFF + r * NSTRIDE + u * 16) = o;
    }

    // ---- Wait for prep grid (full memory visibility) ----------------------
    asm volatile("griddepcontrol.wait;" ::: "memory");

    // ---- cp.async tables: EW+EH 64 rows x 16 chunks each ------------------
    const __half* gW = g_EW + n0 * HDIM;
    const __half* gH = g_EH + n0 * HDIM;
    #pragma unroll
    for (int i = tid; i < 1024; i += 256) {
        const int r = i >> 4, u = i & 15;
        const uint32_t d = r * NSTRIDE + u * 16;
        const int so = r * HDIM + u * 8;
        CP16(sb + EW_OFF + d, gW + so);
        CP16(sb + EH_OFF + d, gH + so);
    }
    CP_COMMIT();
    CP_WAIT0();
    __syncthreads();

    // ---- GEMM: M=64 N=128 K=128, warp tile 32n x 32h ----------------------
    const uint32_t lrow = l & 15, lcol = (l >> 4) * 16;
    const uint32_t aBase = sb + EW_OFF + (wm * 32 + lrow) * NSTRIDE + lcol;
    const uint32_t bBase = sb + ACT_OFF + (wn * 32 + lrow) * NSTRIDE + lcol;

    float acc[2][4][4];
    #pragma unroll
    for (int mt = 0; mt < 2; mt++)
        #pragma unroll
        for (int nt = 0; nt < 4; nt++)
            #pragma unroll
            for (int k = 0; k < 4; k++) acc[mt][nt][k] = 0.0f;

    #pragma unroll
    for (int ks = 0; ks < 8; ks++) {
        const uint32_t koff = ks * 32;
        uint32_t ah[2][4], bv[2][4];
        #pragma unroll
        for (int mt = 0; mt < 2; mt++)
            LDSM_X4(ah[mt][0], ah[mt][1], ah[mt][2], ah[mt][3],
                    aBase + mt * (16 * NSTRIDE) + koff);
        #pragma unroll
        for (int p = 0; p < 2; p++)
            LDSM_X4(bv[p][0], bv[p][1], bv[p][2], bv[p][3],
                    bBase + p * (16 * NSTRIDE) + koff);
        #pragma unroll
        for (int mt = 0; mt < 2; mt++)
            #pragma unroll
            for (int p = 0; p < 2; p++) {
                MMA_F16(acc[mt][2 * p],     ah[mt], bv[p][0], bv[p][2]);
                MMA_F16(acc[mt][2 * p + 1], ah[mt], bv[p][1], bv[p][3]);
            }
    }

    // ---- Epilogue: EhT from smem, quad shuffle, cross-warp reduce ---------
    float rowsum[2][2];
    #pragma unroll
    for (int mt = 0; mt < 2; mt++)
        #pragma unroll
        for (int rh = 0; rh < 2; rh++) {
            const int nloc = wm * 32 + mt * 16 + rh * 8 + (l >> 2);
            const char* eRow = smem + EH_OFF + nloc * NSTRIDE
                             + (wn * 32 + 2 * (l & 3)) * 2;
            float s = 0.0f;
            #pragma unroll
            for (int nt = 0; nt < 4; nt++) {
                const float2 ef = __half22float2(*(const __half2*)(eRow + nt * 16));
                s += acc[mt][nt][rh * 2] * ef.x + acc[mt][nt][rh * 2 + 1] * ef.y;
            }
            s += __shfl_xor_sync(0xFFFFFFFF, s, 1);
            s += __shfl_xor_sync(0xFFFFFFFF, s, 2);
            rowsum[mt][rh] = s;
        }

    float* red = (float*)(smem + RED_OFF);      // [4 wn][64 n]
    if ((l & 3) == 0) {
        #pragma unroll
        for (int mt = 0; mt < 2; mt++)
            #pragma unroll
            for (int rh = 0; rh < 2; rh++) {
                const int nloc = wm * 32 + mt * 16 + rh * 8 + (l >> 2);
                red[wn * 64 + nloc] = rowsum[mt][rh];
            }
    }
    __syncthreads();
    if (tid < 64)
        out[b * NPTS + n0 + tid] =
            (red[tid] + red[64 + tid] + red[128 + tid] + red[192 + tid])
            * 6.103515625e-05f;   // 1/16384
}

// ---------------------------------------------------------------------------
extern "C" void kernel_launch(void* const* d_in, const int* in_sizes, int n_in,
                              void* d_out, int out_size)
{
    const float* act   = (const float*)d_in[0];   // [8,128,128]
    const float* mu    = (const float*)d_in[1];   // [4096,2]
    const float* sigma = (const float*)d_in[2];   // [4096,2]
    float* out = (float*)d_out;                   // [8,64,64]

    cudaFuncSetAttribute(main_kernel,
                         cudaFuncAttributeMaxDynamicSharedMemorySize, SMEM_REQ);

    prep_kernel<<<256, 256>>>(mu, sigma);

    // PDL launch of main (overlaps prep); clean fallback to plain launch.
    cudaLaunchConfig_t cfg = {};
    cfg.gridDim = dim3(NPTS / 64, 8);
    cfg.blockDim = dim3(256);
    cfg.dynamicSmemBytes = SMEM_REQ;
    cfg.stream = 0;
    cudaLaunchAttribute attr[1];
    attr[0].id = cudaLaunchAttributeProgrammaticStreamSerialization;
    attr[0].val.programmaticStreamSerializationAllowed = 1;
    cfg.attrs = attr;
    cfg.numAttrs = 1;
    cudaError_t err = cudaLaunchKernelEx(&cfg, main_kernel, act, (float*)out);
    if (err != cudaSuccess) {
        // griddepcontrol.wait is a no-op without PDL -> plain launch is correct.
        main_kernel<<<dim3(NPTS / 64, 8), 256, SMEM_REQ>>>(act, (float*)out);
    }
}

// round 17
// speedup vs baseline: 1.0022x; 1.0022x over previous
#include <cuda_runtime.h>
#include <cuda_fp16.h>
#include <cstdint>

// Fused single-launch kernel, 4 CTAs/SM single-wave variant:
// corr[b,n] = (1/16384) * sum_h Eh[n,h] * ( sum_w EwT[n,w] * act[b,h,w] )
// CTA = (n-tile 64, single batch): grid 512 @ 4 CTAs/SM (592 slots) = 1 wave.
//   - EwT tile [64n x 128w] fp16 computed in-CTA (32 exps/thread)
//   - act tile [128h x 128w] fp32->fp16 staged in-CTA (LDG.128 x2 -> STS.128)
//   - GEMM M=64 N=128 K=128 (mma.sync.m16n8k16.f16, fp32 accum)
//   - epilogue: Eh computed on the fly in fp32 (32 exps/thread)

#define HDIM 128
#define NPTS 4096

// Rows padded to 272B = 17*16 -> ldmatrix lane addrs conflict-free.
#define NSTRIDE  272
#define EW_OFF   0
#define ACT_OFF  17408                 // 64*272
#define MUX_OFF  52224                 // +128*272
#define INVX_OFF 52480
#define RED_OFF  52736                 // 4*64 floats
#define SMEM_REQ 53760                 // x4 CTAs = 215K <= 228K

__device__ __forceinline__ uint32_t smem_to_u32(const void* p) {
    uint32_t a;
    asm("{ .reg .u64 t; cvta.to.shared.u64 t, %1; cvt.u32.u64 %0, t; }" : "=r"(a) : "l"(p));
    return a;
}
__device__ __forceinline__ uint32_t f22h2(float a, float b) {
    __half2 h = __floats2half2_rn(a, b);
    return *reinterpret_cast<uint32_t*>(&h);
}

#define LDSM_X4(r0, r1, r2, r3, addr)                                          \
    asm volatile("ldmatrix.sync.aligned.m8n8.x4.shared.b16 {%0,%1,%2,%3}, [%4];" \
        : "=r"(r0), "=r"(r1), "=r"(r2), "=r"(r3) : "r"(addr))

#define MMA_F16(c, a, b0, b1)                                                  \
    asm volatile("mma.sync.aligned.m16n8k16.row.col.f32.f16.f16.f32 "           \
        "{%0,%1,%2,%3},{%4,%5,%6,%7},{%8,%9},{%0,%1,%2,%3};"                    \
        : "+f"((c)[0]), "+f"((c)[1]), "+f"((c)[2]), "+f"((c)[3])                \
        : "r"((a)[0]), "r"((a)[1]), "r"((a)[2]), "r"((a)[3]), "r"(b0), "r"(b1))

__global__ __launch_bounds__(256, 4) void fused_kernel(
    const float* __restrict__ act,    // [8,128,128]
    const float* __restrict__ mu,     // [4096,2]
    const float* __restrict__ sigma,  // [4096,2]
    float* __restrict__ out)          // [8,4096]
{
    extern __shared__ char smem[];
    const uint32_t sb = smem_to_u32(smem);

    const int tid = threadIdx.x;
    const int wid = tid >> 5, l = tid & 31;
    const int wm = wid & 1;            // n half: rows wm*32..+32
    const int wn = wid >> 1;           // h quarter: cols wn*32..+32
    const int b  = blockIdx.y;
    const int n0 = blockIdx.x * 64;

    // Table parameters (issue mu/sigma LDG early)
    const int en = tid >> 2;                    // table row (local n) 0..63
    const int qd = tid & 3;                     // 32-col quarter
    const float2 m = ((const float2*)mu)[n0 + en];
    const float2 s = ((const float2*)sigma)[n0 + en];

    // ---- Stage act: 8 chunks/thread (2x LDG.128 fp32 -> 1x STS.128 fp16) --
    const float4* g0p = (const float4*)(act + b * HDIM * HDIM);
    #pragma unroll
    for (int k = 0; k < 8; k++) {
        const int cid = k * 256 + tid;          // 0..2047 16B-chunks
        const int r = cid >> 4, u = cid & 15;
        const float4 va = __ldg(&g0p[r * 32 + u * 2]);
        const float4 vb = __ldg(&g0p[r * 32 + u * 2 + 1]);
        uint4 o;
        o.x = f22h2(va.x, va.y); o.y = f22h2(va.z, va.w);
        o.z = f22h2(vb.x, vb.y); o.w = f22h2(vb.z, vb.w);
        *(uint4*)(smem + ACT_OFF + r * NSTRIDE + u * 16) = o;
    }

    // ---- EwT tile (32 exps/thread) + mux/invx epilogue cache --------------
    {
        const float invy = 1.0f / (2.0f * s.y * s.y);
        const float invx = 1.0f / (2.0f * s.x * s.x);
        if (qd == 0) {
            *(float*)(smem + MUX_OFF + en * 4)  = m.x;
            *(float*)(smem + INVX_OFF + en * 4) = invx;
        }
        char* rowW = smem + EW_OFF + en * NSTRIDE + qd * 64;
        const float j0 = (float)(qd * 32) * (1.0f / 128.0f);
        #pragma unroll
        for (int c4 = 0; c4 < 8; c4++) {
            float ew[4];
            #pragma unroll
            for (int j = 0; j < 4; j++) {
                const float dy =
                    j0 + (float)(c4 * 4 + j) * (1.0f / 128.0f) - m.y;
                ew[j] = __expf(-(dy * dy * invy));
            }
            ((__half2*)(rowW + c4 * 8))[0] = __floats2half2_rn(ew[0], ew[1]);
            ((__half2*)(rowW + c4 * 8))[1] = __floats2half2_rn(ew[2], ew[3]);
        }
    }
    __syncthreads();

    // ---- GEMM: M=64 N=128 K=128, warp tile 32n x 32h ----------------------
    const uint32_t lrow = l & 15, lcol = (l >> 4) * 16;
    const uint32_t aBase = sb + EW_OFF + (wm * 32 + lrow) * NSTRIDE + lcol;
    const uint32_t bBase = sb + ACT_OFF + (wn * 32 + lrow) * NSTRIDE + lcol;

    float acc[2][4][4];
    #pragma unroll
    for (int mt = 0; mt < 2; mt++)
        #pragma unroll
        for (int nt = 0; nt < 4; nt++)
            #pragma unroll
            for (int k = 0; k < 4; k++) acc[mt][nt][k] = 0.0f;

    #pragma unroll
    for (int ks = 0; ks < 8; ks++) {
        const uint32_t koff = ks * 32;
        uint32_t ah[2][4], bv[2][4];
        #pragma unroll
        for (int mt = 0; mt < 2; mt++)
            LDSM_X4(ah[mt][0], ah[mt][1], ah[mt][2], ah[mt][3],
                    aBase + mt * (16 * NSTRIDE) + koff);
        #pragma unroll
        for (int p = 0; p < 2; p++)
            LDSM_X4(bv[p][0], bv[p][1], bv[p][2], bv[p][3],
                    bBase + p * (16 * NSTRIDE) + koff);
        #pragma unroll
        for (int mt = 0; mt < 2; mt++)
            #pragma unroll
            for (int p = 0; p < 2; p++) {
                MMA_F16(acc[mt][2 * p],     ah[mt], bv[p][0], bv[p][2]);
                MMA_F16(acc[mt][2 * p + 1], ah[mt], bv[p][1], bv[p][3]);
            }
    }

    // ---- Epilogue: Eh on the fly (fp32), quad shuffle, smem reduce --------
    // D rows: nloc = wm*32 + mt*16 + rh*8 + l/4; cols h = wn*32 + nt*8 + 2(l&3)+{0,1}
    const float h0f = (float)(wn * 32 + 2 * (l & 3)) * (1.0f / 128.0f);
    float rowsum[2][2];
    #pragma unroll
    for (int mt = 0; mt < 2; mt++)
        #pragma unroll
        for (int rh = 0; rh < 2; rh++) {
            const int nloc = wm * 32 + mt * 16 + rh * 8 + (l >> 2);
            const float a   = *(const float*)(smem + MUX_OFF + nloc * 4);
            const float inv = *(const float*)(smem + INVX_OFF + nloc * 4);
            float sum = 0.0f;
            #pragma unroll
            for (int nt = 0; nt < 4; nt++) {
                const float d0 = h0f + (float)nt * (8.0f / 128.0f) - a;
                const float d1 = d0 + (1.0f / 128.0f);
                const float e0 = __expf(-(d0 * d0 * inv));
                const float e1 = __expf(-(d1 * d1 * inv));
                sum += acc[mt][nt][rh * 2] * e0 + acc[mt][nt][rh * 2 + 1] * e1;
            }
            sum += __shfl_xor_sync(0xFFFFFFFF, sum, 1);
            sum += __shfl_xor_sync(0xFFFFFFFF, sum, 2);
            rowsum[mt][rh] = sum;
        }

    float* red = (float*)(smem + RED_OFF);      // [4 wn][64 n]
    if ((l & 3) == 0) {
        #pragma unroll
        for (int mt = 0; mt < 2; mt++)
            #pragma unroll
            for (int rh = 0; rh < 2; rh++) {
                const int nloc = wm * 32 + mt * 16 + rh * 8 + (l >> 2);
                red[wn * 64 + nloc] = rowsum[mt][rh];
            }
    }
    __syncthreads();
    if (tid < 64)
        out[b * NPTS + n0 + tid] =
            (red[tid] + red[64 + tid] + red[128 + tid] + red[192 + tid])
            * 6.103515625e-05f;   // 1/16384
}

// ---------------------------------------------------------------------------
extern "C" void kernel_launch(void* const* d_in, const int* in_sizes, int n_in,
                              void* d_out, int out_size)
{
    const float* act   = (const float*)d_in[0];   // [8,128,128]
    const float* mu    = (const float*)d_in[1];   // [4096,2]
    const float* sigma = (const float*)d_in[2];   // [4096,2]
    float* out = (float*)d_out;                   // [8,64,64]

    cudaFuncSetAttribute(fused_kernel,
                         cudaFuncAttributeMaxDynamicSharedMemorySize, SMEM_REQ);

    fused_kernel<<<dim3(NPTS / 64, 8), 256, SMEM_REQ>>>(act, mu, sigma, out);
}